// round 14
// baseline (speedup 1.0000x reference)
#include <cuda_runtime.h>
#include <cuda_bf16.h>
#include <cstdint>
#include <math.h>

#define NMAX 50000
#define EMAX 800000

// ---------------- device scratch ------------------------------------------
__device__ int   g_is64;
__device__ int   g_degi[NMAX];
__device__ int   g_row[NMAX + 1];
__device__ int   g_cursor[NMAX];
__device__ float g_inv[NMAX];
__device__ int   g_csr[EMAX];
__device__ int   g_bsum[64];
__device__ int   g_tilecnt[1024];      // per-64-row-tile arrival counters (self-zeroing)
__device__ float g_mean[(size_t)NMAX * 128];
__device__ float g_h1[(size_t)NMAX * 128];
__device__ float g_h2[(size_t)NMAX * 128];
// W^T bf16 images per matrix slot: hi at +0, lo at +32768 bytes (row-major [OUT][128])
__device__ uint4 g_wt[8][4096];

// ---------------- helpers ----------------------------------------------------
__device__ __forceinline__ uint32_t smem_u32(const void* p) {
    uint32_t a;
    asm("{ .reg .u64 t; cvta.to.shared.u64 t, %1; cvt.u32.u64 %0, t; }"
        : "=r"(a) : "l"(p));
    return a;
}
__device__ __forceinline__ uint32_t pack2bf(float x, float y) {
    __nv_bfloat162 t = __floats2bfloat162_rn(x, y);
    return *reinterpret_cast<uint32_t*>(&t);
}
__device__ __forceinline__ void ldsm_x4(uint32_t addr, uint32_t& r0, uint32_t& r1,
                                        uint32_t& r2, uint32_t& r3) {
    asm volatile("ldmatrix.sync.aligned.m8n8.x4.shared.b16 {%0,%1,%2,%3}, [%4];"
                 : "=r"(r0), "=r"(r1), "=r"(r2), "=r"(r3) : "r"(addr));
}
__device__ __forceinline__ void mma_bf16(float (&c)[4], const uint32_t (&a)[4],
                                         uint32_t b0, uint32_t b1) {
    asm volatile(
        "mma.sync.aligned.m16n8k16.row.col.f32.bf16.bf16.f32 "
        "{%0,%1,%2,%3}, {%4,%5,%6,%7}, {%8,%9}, {%0,%1,%2,%3};"
        : "+f"(c[0]), "+f"(c[1]), "+f"(c[2]), "+f"(c[3])
        : "r"(a[0]), "r"(a[1]), "r"(a[2]), "r"(a[3]), "r"(b0), "r"(b1));
}
__device__ __forceinline__ void cp_async16(uint32_t dst, const void* src) {
    asm volatile("cp.async.cg.shared.global [%0], [%1], 16;"
                 :: "r"(dst), "l"(src) : "memory");
}
#define CP_COMMIT() asm volatile("cp.async.commit_group;" ::: "memory")
#define CP_WAIT(n)  asm volatile("cp.async.wait_group %0;" :: "n"(n) : "memory")

// ---------------- init: zero degrees + index-width detect -------------------
// jax "int64" silently becomes int32 when x64 is disabled; detect on-device.
__global__ void init_kernel(const unsigned long long* __restrict__ p, int n) {
    int i = blockIdx.x * blockDim.x + threadIdx.x;
    if (i < n) g_degi[i] = 0;
    if (i == 0) {
        int is64 = 1;
        #pragma unroll
        for (int k = 0; k < 8; k++)
            if (p[k] >= 50000ULL) is64 = 0;
        g_is64 = is64;
    }
}

__device__ __forceinline__ int load_edge(const void* ei, int pos, int is64) {
    if (is64) return (int)((const long long*)ei)[pos];
    return ((const int*)ei)[pos];
}

__global__ void hist_kernel(const void* __restrict__ ei, int E) {
    int e = blockIdx.x * blockDim.x + threadIdx.x;
    if (e < E) {
        int dst = load_edge(ei, E + e, g_is64);
        atomicAdd(&g_degi[dst], 1);
    }
}

__global__ void bsum_kernel(int n) {
    __shared__ int ws[8];
    int b = blockIdx.x, tid = threadIdx.x;
    int v = 0;
    int base = b * 1024;
    for (int i = tid; i < 1024; i += 256) {
        int idx = base + i;
        if (idx < n) v += g_degi[idx];
    }
    #pragma unroll
    for (int off = 16; off; off >>= 1) v += __shfl_down_sync(0xffffffffu, v, off);
    if ((tid & 31) == 0) ws[tid >> 5] = v;
    __syncthreads();
    if (tid == 0) {
        int s = 0;
        #pragma unroll
        for (int k = 0; k < 8; k++) s += ws[k];
        g_bsum[b] = s;
    }
}

__global__ void scan2_kernel(int n) {
    __shared__ int wsum[32];
    __shared__ int part[2];
    int b = blockIdx.x, tid = threadIdx.x;
    int lane = tid & 31, w = tid >> 5;
    if (tid < 64) {
        int v = (tid < b) ? g_bsum[tid] : 0;
        #pragma unroll
        for (int off = 16; off; off >>= 1) v += __shfl_down_sync(0xffffffffu, v, off);
        if ((tid & 31) == 0) part[tid >> 5] = v;
    }
    int i = b * 1024 + tid;
    int v = (i < n) ? g_degi[i] : 0;
    int incl = v;
    #pragma unroll
    for (int off = 1; off < 32; off <<= 1) {
        int t = __shfl_up_sync(0xffffffffu, incl, off);
        if (lane >= off) incl += t;
    }
    if (lane == 31) wsum[w] = incl;
    __syncthreads();
    if (w == 0) {
        int t = wsum[lane];
        #pragma unroll
        for (int off = 1; off < 32; off <<= 1) {
            int u = __shfl_up_sync(0xffffffffu, t, off);
            if (lane >= off) t += u;
        }
        wsum[lane] = t;
    }
    __syncthreads();
    int boff = part[0] + part[1];
    int excl = boff + ((w == 0) ? 0 : wsum[w - 1]) + incl - v;
    if (i < n) {
        g_row[i]    = excl;
        g_cursor[i] = excl;
        g_inv[i]    = 1.0f / fmaxf((float)v, 1.0f);
        if (i == n - 1) g_row[n] = excl + v;
    }
}

__global__ void fill_kernel(const void* __restrict__ ei, int E) {
    int e = blockIdx.x * blockDim.x + threadIdx.x;
    if (e < E) {
        int is64 = g_is64;
        int src = load_edge(ei, e, is64);
        int dst = load_edge(ei, E + e, is64);
        int pos = atomicAdd(&g_cursor[dst], 1);
        g_csr[pos] = src;
    }
}

// ---------------- W^T prep: hi/lo bf16 split, row-major [OUT][128] ----------
__global__ void prep_w_kernel(const float* w1n, const float* w1r,
                              const float* w2n, const float* w2r,
                              const float* wr1, const float* wfn,
                              const float* wfr, const float* wr2) {
    int m = blockIdx.x;
    const float* W;
    switch (m) {
        case 0: W = w1n; break; case 1: W = w1r; break;
        case 2: W = w2n; break; case 3: W = w2r; break;
        case 4: W = wr1; break; case 5: W = wfn; break;
        case 6: W = wfr; break; default: W = wr2; break;
    }
    int OUT = (m < 5) ? 128 : 64;
    unsigned short* hi = (unsigned short*)&g_wt[m][0];
    unsigned short* lo = (unsigned short*)((char*)&g_wt[m][0] + 32768);
    for (int idx = threadIdx.x; idx < 128 * OUT; idx += blockDim.x) {
        int k = idx / OUT, nn = idx % OUT;       // W row-major [128][OUT]
        float v = W[idx];
        __nv_bfloat16 h = __float2bfloat16(v);
        __nv_bfloat16 l = __float2bfloat16(v - __bfloat162float(h));
        hi[nn * 128 + k] = *reinterpret_cast<unsigned short*>(&h);
        lo[nn * 128 + k] = *reinterpret_cast<unsigned short*>(&l);
    }
}

// ---------------- fused gather + layer kernel --------------------------------
// Grid = 9 * LB blocks. bid%9 != 8 -> gather block (8 nodes, warp/node).
// bid%9 == 8 -> layer block for tile bid/9 (64 rows, 128 active threads).
// Gather blocks write mean rows + bump per-tile counters (release);
// layer blocks spin (acquire) on their tile counter before the mean stream,
// then reset it to 0 so counters are all-zero at kernel exit (graph-replay safe).
// Producers of tile t (gather blocks 8t..8t+7, bids 9t..9t+7) always have lower
// blockIdx than their consumer (bid 9t+8) -> in-order dispatch => no deadlock.
template<int N, int NS, int MEAN_S, bool RELU_MID, bool RELU_END, bool HASB2, bool SIG>
__global__ void __launch_bounds__(256, 2)
fused_layer_kernel(const float* __restrict__ xg, float* __restrict__ meanout,
                   const float* __restrict__ A0, const float* __restrict__ A1,
                   const float* __restrict__ A2,
                   const uint4* __restrict__ T0, const uint4* __restrict__ T1,
                   const uint4* __restrict__ T2,
                   const float* __restrict__ biasA, const float* __restrict__ biasB,
                   float* __restrict__ out, int n) {
    int bid = blockIdx.x;
    int tid = threadIdx.x, wid = tid >> 5, lane = tid & 31;

    if ((bid % 9) != 8) {
        // ---------------- gather role ----------------
        int gid = bid - bid / 9;
        int node = gid * 8 + wid;
        if (node >= n) return;
        int start = g_row[node];
        int end   = g_row[node + 1];
        const float4* __restrict__ x4 = (const float4*)xg;
        float4 a0 = make_float4(0.f, 0.f, 0.f, 0.f);
        float4 a1 = make_float4(0.f, 0.f, 0.f, 0.f);
        for (int j0 = start; j0 < end; j0 += 32) {
            int cnt = min(32, end - j0);
            int myidx = (lane < cnt) ? g_csr[j0 + lane] : 0;
            int j = 0;
            for (; j + 4 <= cnt; j += 4) {
                int s0 = __shfl_sync(0xffffffffu, myidx, j + 0);
                int s1 = __shfl_sync(0xffffffffu, myidx, j + 1);
                int s2 = __shfl_sync(0xffffffffu, myidx, j + 2);
                int s3 = __shfl_sync(0xffffffffu, myidx, j + 3);
                float4 v0 = __ldg(&x4[s0 * 32 + lane]);
                float4 v1 = __ldg(&x4[s1 * 32 + lane]);
                float4 v2 = __ldg(&x4[s2 * 32 + lane]);
                float4 v3 = __ldg(&x4[s3 * 32 + lane]);
                a0.x += v0.x; a0.y += v0.y; a0.z += v0.z; a0.w += v0.w;
                a1.x += v1.x; a1.y += v1.y; a1.z += v1.z; a1.w += v1.w;
                a0.x += v2.x; a0.y += v2.y; a0.z += v2.z; a0.w += v2.w;
                a1.x += v3.x; a1.y += v3.y; a1.z += v3.z; a1.w += v3.w;
            }
            for (; j < cnt; j++) {
                int s0 = __shfl_sync(0xffffffffu, myidx, j);
                float4 v0 = __ldg(&x4[s0 * 32 + lane]);
                a0.x += v0.x; a0.y += v0.y; a0.z += v0.z; a0.w += v0.w;
            }
        }
        float inv = g_inv[node];
        float4 r;
        r.x = (a0.x + a1.x) * inv;
        r.y = (a0.y + a1.y) * inv;
        r.z = (a0.z + a1.z) * inv;
        r.w = (a0.w + a1.w) * inv;
        ((float4*)meanout)[node * 32 + lane] = r;
        __syncwarp();
        if (lane == 0) {
            __threadfence();
            atomicAdd(&g_tilecnt[node >> 6], 1);
        }
        return;
    }

    // ---------------- layer role ----------------
    int layerId = bid / 9;
    int tileBase = layerId * 64;
    if (tileBase >= n) return;
    if (tid >= 128) return;            // 4 active warps

    extern __shared__ unsigned char smem[];
    const int WTILE = N * 256;
    float* sBiasA = (float*)smem;
    float* sBiasB = (float*)(smem + 512);
    unsigned char* sAhi = smem + 1024;           // 16 KB (64 rows x 256 B)
    unsigned char* sAlo = sAhi + 16384;          // 16 KB
    unsigned char* sWhi = sAlo + 16384;          // WTILE
    unsigned char* sWlo = sWhi + WTILE;          // WTILE
    uint32_t uAhi = smem_u32(sAhi), uAlo = smem_u32(sAlo);
    uint32_t uWhi = smem_u32(sWhi), uWlo = smem_u32(sWlo);

    if (tid < N) {
        sBiasA[tid] = biasA[tid];
        if (HASB2) sBiasB[tid] = biasB[tid];
    }

    const float* As[3] = {A0, A1, A2};
    const uint4* Ts[3] = {T0, T1, T2};

    float acc[N / 8][4];
    #pragma unroll
    for (int nc = 0; nc < N / 8; nc++)
        #pragma unroll
        for (int j = 0; j < 4; j++) acc[nc][j] = 0.f;

    int arow = (wid << 4) + (lane & 15);                 // 0..63
    uint32_t aoffBase = (uint32_t)arow * 256 + ((lane >> 4) << 4);
    uint32_t aswz = (uint32_t)(arow & 7) << 4;
    int brow_loc = (lane & 7) + ((lane >> 4) << 3);
    uint32_t bkoff = (lane & 8) ? 16u : 0u;
    uint32_t bswz = (uint32_t)(brow_loc & 7) << 4;

    #pragma unroll
    for (int s = 0; s < NS; s++) {
        __syncthreads();   // previous compute done before smem overwrite
        // stage W^T hi/lo via cp.async (swizzled)
        {
            const uint4* srcH = Ts[s];
            const uint4* srcL = Ts[s] + 2048;
            #pragma unroll
            for (int u0 = 0; u0 < N * 16; u0 += 128) {
                int u = u0 + tid;
                int nr = u >> 4;
                uint32_t off = ((uint32_t)u * 16) ^ ((uint32_t)(nr & 7) << 4);
                cp_async16(uWhi + off, srcH + u);
                cp_async16(uWlo + off, srcL + u);
            }
            CP_COMMIT();
        }
        // gate on gather completion before touching the mean stream's input
        if (s == MEAN_S) {
            if (tid == 0) {
                int tgt = min(64, n - tileBase);
                while (*(volatile int*)&g_tilecnt[layerId] < tgt) {}
                g_tilecnt[layerId] = 0;     // self-zero for next launch
                __threadfence();
            }
            __syncthreads();
        }
        // stage A: 64 rows x 128 cols, fp32 -> bf16 hi/lo, swizzled
        {
            const float* A = As[s];
            #pragma unroll
            for (int i = 0; i < 8; i++) {
                int u = i * 128 + tid;        // 0..1023
                int row = u >> 4, kc = u & 15;
                int grow = tileBase + row;
                grow = (grow < n) ? grow : (n - 1);
                const float4* src = (const float4*)(A + (size_t)grow * 128 + kc * 8);
                float4 v0 = __ldg(src);
                float4 v1 = __ldg(src + 1);
                float h[8], l[8];
                #pragma unroll
                for (int j = 0; j < 8; j++) {
                    float x = (j < 4) ? (&v0.x)[j] : (&v1.x)[j - 4];
                    __nv_bfloat16 hb = __float2bfloat16(x);
                    h[j] = __bfloat162float(hb);
                    l[j] = x - h[j];
                }
                uint4 ph, pl;
                ph.x = pack2bf(h[0], h[1]); ph.y = pack2bf(h[2], h[3]);
                ph.z = pack2bf(h[4], h[5]); ph.w = pack2bf(h[6], h[7]);
                pl.x = pack2bf(l[0], l[1]); pl.y = pack2bf(l[2], l[3]);
                pl.z = pack2bf(l[4], l[5]); pl.w = pack2bf(l[6], l[7]);
                uint32_t off = ((uint32_t)u * 16) ^ ((uint32_t)(row & 7) << 4);
                *(uint4*)(sAhi + off) = ph;
                *(uint4*)(sAlo + off) = pl;
            }
        }
        CP_WAIT(0);
        __syncthreads();

        // compute: 8 k-chunks of 16
        #pragma unroll
        for (int kc = 0; kc < 8; kc++) {
            uint32_t ah[4], al[4];
            uint32_t aoff = ((aoffBase + kc * 32) ^ aswz);
            ldsm_x4(uAhi + aoff, ah[0], ah[1], ah[2], ah[3]);
            ldsm_x4(uAlo + aoff, al[0], al[1], al[2], al[3]);
            #pragma unroll
            for (int np = 0; np < N / 16; np++) {
                uint32_t boff = (((uint32_t)(np * 16 + brow_loc) * 256
                                  + kc * 32 + bkoff) ^ bswz);
                uint32_t bh0, bh1, bh2, bh3, bl0, bl1, bl2, bl3;
                ldsm_x4(uWhi + boff, bh0, bh1, bh2, bh3);
                ldsm_x4(uWlo + boff, bl0, bl1, bl2, bl3);
                mma_bf16(acc[2 * np],     ah, bh0, bh1);
                mma_bf16(acc[2 * np],     ah, bl0, bl1);
                mma_bf16(acc[2 * np],     al, bh0, bh1);
                mma_bf16(acc[2 * np + 1], ah, bh2, bh3);
                mma_bf16(acc[2 * np + 1], ah, bl2, bl3);
                mma_bf16(acc[2 * np + 1], al, bh2, bh3);
            }
        }

        // mid bias + relu after stream 1 (applies to streams 0+1 partial sum)
        if (RELU_MID && s == 1) {
            #pragma unroll
            for (int nc = 0; nc < N / 8; nc++) {
                int c = nc * 8 + (lane & 3) * 2;
                float b0 = sBiasA[c], b1 = sBiasA[c + 1];
                acc[nc][0] = fmaxf(acc[nc][0] + b0, 0.f);
                acc[nc][1] = fmaxf(acc[nc][1] + b1, 0.f);
                acc[nc][2] = fmaxf(acc[nc][2] + b0, 0.f);
                acc[nc][3] = fmaxf(acc[nc][3] + b1, 0.f);
            }
        }
    }

    // epilogue
    int r0 = tileBase + (wid << 4) + (lane >> 2);
    int r1 = r0 + 8;
    #pragma unroll
    for (int nc = 0; nc < N / 8; nc++) {
        int c = nc * 8 + (lane & 3) * 2;
        float bA0 = RELU_MID ? 0.f : sBiasA[c];
        float bA1 = RELU_MID ? 0.f : sBiasA[c + 1];
        float bB0 = HASB2 ? sBiasB[c] : 0.f;
        float bB1 = HASB2 ? sBiasB[c + 1] : 0.f;
        #pragma unroll
        for (int half = 0; half < 2; half++) {
            int row = half ? r1 : r0;
            if (row >= n) continue;
            float v0 = acc[nc][2 * half]     + bA0;
            float v1 = acc[nc][2 * half + 1] + bA1;
            if (RELU_END) { v0 = fmaxf(v0, 0.f); v1 = fmaxf(v1, 0.f); }
            v0 += bB0; v1 += bB1;
            if (SIG && c < 8) {
                v0 = 1.0f / (1.0f + expf(-v0));
                v1 = 1.0f / (1.0f + expf(-v1));
            }
            *(float2*)(out + (size_t)row * N + c) = make_float2(v0, v1);
        }
    }
}

// ---------------- launch ----------------------------------------------------
extern "C" void kernel_launch(void* const* d_in, const int* in_sizes, int n_in,
                              void* d_out, int out_size) {
    const float* z   = (const float*)d_in[0];
    const void*  ei  = d_in[1];
    const float* w1n = (const float*)d_in[2];
    const float* w1r = (const float*)d_in[3];
    const float* b1  = (const float*)d_in[4];
    const float* w2n = (const float*)d_in[5];
    const float* w2r = (const float*)d_in[6];
    const float* b2  = (const float*)d_in[7];
    const float* wfn = (const float*)d_in[8];
    const float* wfr = (const float*)d_in[9];
    const float* bf  = (const float*)d_in[10];
    const float* wr1 = (const float*)d_in[11];
    const float* br1 = (const float*)d_in[12];
    const float* wr2 = (const float*)d_in[13];
    const float* br2 = (const float*)d_in[14];

    int n = in_sizes[0] / 128;
    int E = in_sizes[1] / 2;
    float* out = (float*)d_out;

    float *p_mean, *p_h1, *p_h2;
    uint4* p_wt;
    cudaGetSymbolAddress((void**)&p_mean, g_mean);
    cudaGetSymbolAddress((void**)&p_h1, g_h1);
    cudaGetSymbolAddress((void**)&p_h2, g_h2);
    cudaGetSymbolAddress((void**)&p_wt, g_wt);

    const int smemN128 = 1024 + 32768 + 2 * 128 * 256;   // 99328 B (97 KB)
    const int smemN64  = 1024 + 32768 + 2 * 64 * 256;    // 66560 B (65 KB)
    cudaFuncSetAttribute(fused_layer_kernel<128, 2, 1, false, true, false, false>,
                         cudaFuncAttributeMaxDynamicSharedMemorySize, smemN128);
    cudaFuncSetAttribute(fused_layer_kernel<128, 3, 1, true, false, true, false>,
                         cudaFuncAttributeMaxDynamicSharedMemorySize, smemN128);
    cudaFuncSetAttribute(fused_layer_kernel<64, 3, 2, false, false, true, true>,
                         cudaFuncAttributeMaxDynamicSharedMemorySize, smemN64);

    int nb = (n + 1023) / 1024;
    int LB = (n + 63) / 64;               // layer tiles (64 rows)
    int grid = 9 * LB;                    // 8 gather blocks : 1 layer block
    #define WT(i) (p_wt + (size_t)(i) * 4096)

    // weight prep + CSR build (proven R7 path)
    prep_w_kernel<<<8, 256>>>(w1n, w1r, w2n, w2r, wr1, wfn, wfr, wr2);
    init_kernel<<<(n + 255) / 256, 256>>>((const unsigned long long*)ei, n);
    hist_kernel<<<(E + 255) / 256, 256>>>(ei, E);
    bsum_kernel<<<nb, 256>>>(n);
    scan2_kernel<<<nb, 1024>>>(n);
    fill_kernel<<<(E + 255) / 256, 256>>>(ei, E);

    // layer 1: h1 = relu(z @ w1r + mean(z) @ w1n + b1)
    fused_layer_kernel<128, 2, 1, false, true, false, false><<<grid, 256, smemN128>>>(
        z, p_mean, z, p_mean, nullptr, WT(1), WT(0), nullptr,
        b1, nullptr, p_h1, n);

    // layer 2: h2 = relu(h1 @ w2r + mean(h1) @ w2n + b2) + z @ wr1 + br1
    fused_layer_kernel<128, 3, 1, true, false, true, false><<<grid, 256, smemN128>>>(
        p_h1, p_mean, p_h1, p_mean, z, WT(3), WT(2), WT(4),
        b2, br1, p_h2, n);

    // layer 3: out = h2 @ wfr + z @ wr2 + mean(h2) @ wfn + bf + br2; sigmoid[:8]
    fused_layer_kernel<64, 3, 2, false, false, true, true><<<grid, 256, smemN64>>>(
        p_h2, p_mean, p_h2, z, p_mean, WT(6), WT(7), WT(5),
        bf, br2, out, n);
}

// round 15
// speedup vs baseline: 1.6147x; 1.6147x over previous
#include <cuda_runtime.h>
#include <cuda_bf16.h>
#include <cuda_fp16.h>
#include <cstdint>
#include <math.h>

#define NMAX 50000
#define EMAX 800000

// ---------------- device scratch ------------------------------------------
__device__ int    g_is64;
__device__ int    g_degi[NMAX];
__device__ int    g_row[NMAX + 1];
__device__ int    g_cursor[NMAX];
__device__ float  g_inv[NMAX];
__device__ int    g_csr[EMAX];
__device__ int    g_bsum[64];
__device__ float  g_mean[(size_t)NMAX * 128];
__device__ float  g_h1[(size_t)NMAX * 128];
__device__ float  g_h2[(size_t)NMAX * 128];
__device__ __half g_zh[(size_t)NMAX * 128];    // fp16 copies for gather reads
__device__ __half g_h1h[(size_t)NMAX * 128];
__device__ __half g_h2h[(size_t)NMAX * 128];
// W^T bf16 images per matrix slot: hi at +0, lo at +32768 bytes (row-major [OUT][128])
__device__ uint4 g_wt[8][4096];

// ---------------- helpers ----------------------------------------------------
__device__ __forceinline__ uint32_t smem_u32(const void* p) {
    uint32_t a;
    asm("{ .reg .u64 t; cvta.to.shared.u64 t, %1; cvt.u32.u64 %0, t; }"
        : "=r"(a) : "l"(p));
    return a;
}
__device__ __forceinline__ uint32_t pack2bf(float x, float y) {
    __nv_bfloat162 t = __floats2bfloat162_rn(x, y);
    return *reinterpret_cast<uint32_t*>(&t);
}
__device__ __forceinline__ void ldsm_x4(uint32_t addr, uint32_t& r0, uint32_t& r1,
                                        uint32_t& r2, uint32_t& r3) {
    asm volatile("ldmatrix.sync.aligned.m8n8.x4.shared.b16 {%0,%1,%2,%3}, [%4];"
                 : "=r"(r0), "=r"(r1), "=r"(r2), "=r"(r3) : "r"(addr));
}
__device__ __forceinline__ void mma_bf16(float (&c)[4], const uint32_t (&a)[4],
                                         uint32_t b0, uint32_t b1) {
    asm volatile(
        "mma.sync.aligned.m16n8k16.row.col.f32.bf16.bf16.f32 "
        "{%0,%1,%2,%3}, {%4,%5,%6,%7}, {%8,%9}, {%0,%1,%2,%3};"
        : "+f"(c[0]), "+f"(c[1]), "+f"(c[2]), "+f"(c[3])
        : "r"(a[0]), "r"(a[1]), "r"(a[2]), "r"(a[3]), "r"(b0), "r"(b1));
}
__device__ __forceinline__ void cp_async16(uint32_t dst, const void* src) {
    asm volatile("cp.async.cg.shared.global [%0], [%1], 16;"
                 :: "r"(dst), "l"(src) : "memory");
}
#define CP_COMMIT() asm volatile("cp.async.commit_group;" ::: "memory")
#define CP_WAIT(n)  asm volatile("cp.async.wait_group %0;" :: "n"(n) : "memory")

// ---------------- init: zero degrees + index-width detect -------------------
// jax "int64" silently becomes int32 when x64 is disabled; detect on-device.
__global__ void init_kernel(const unsigned long long* __restrict__ p, int n) {
    int i = blockIdx.x * blockDim.x + threadIdx.x;
    if (i < n) g_degi[i] = 0;
    if (i == 0) {
        int is64 = 1;
        #pragma unroll
        for (int k = 0; k < 8; k++)
            if (p[k] >= 50000ULL) is64 = 0;
        g_is64 = is64;
    }
}

// ---------------- z -> fp16 copy ---------------------------------------------
__global__ void tohalf_kernel(const float* __restrict__ src,
                              __half* __restrict__ dst, int total4) {
    int i = blockIdx.x * blockDim.x + threadIdx.x;
    if (i < total4) {
        float4 v = __ldg((const float4*)src + i);
        __half2 h0 = __floats2half2_rn(v.x, v.y);
        __half2 h1 = __floats2half2_rn(v.z, v.w);
        uint2 u;
        u.x = *reinterpret_cast<uint32_t*>(&h0);
        u.y = *reinterpret_cast<uint32_t*>(&h1);
        ((uint2*)dst)[i] = u;
    }
}

__device__ __forceinline__ int load_edge(const void* ei, int pos, int is64) {
    if (is64) return (int)((const long long*)ei)[pos];
    return ((const int*)ei)[pos];
}

__global__ void hist_kernel(const void* __restrict__ ei, int E) {
    int e = blockIdx.x * blockDim.x + threadIdx.x;
    if (e < E) {
        int dst = load_edge(ei, E + e, g_is64);
        atomicAdd(&g_degi[dst], 1);
    }
}

__global__ void bsum_kernel(int n) {
    __shared__ int ws[8];
    int b = blockIdx.x, tid = threadIdx.x;
    int v = 0;
    int base = b * 1024;
    for (int i = tid; i < 1024; i += 256) {
        int idx = base + i;
        if (idx < n) v += g_degi[idx];
    }
    #pragma unroll
    for (int off = 16; off; off >>= 1) v += __shfl_down_sync(0xffffffffu, v, off);
    if ((tid & 31) == 0) ws[tid >> 5] = v;
    __syncthreads();
    if (tid == 0) {
        int s = 0;
        #pragma unroll
        for (int k = 0; k < 8; k++) s += ws[k];
        g_bsum[b] = s;
    }
}

__global__ void scan2_kernel(int n) {
    __shared__ int wsum[32];
    __shared__ int part[2];
    int b = blockIdx.x, tid = threadIdx.x;
    int lane = tid & 31, w = tid >> 5;
    if (tid < 64) {
        int v = (tid < b) ? g_bsum[tid] : 0;
        #pragma unroll
        for (int off = 16; off; off >>= 1) v += __shfl_down_sync(0xffffffffu, v, off);
        if ((tid & 31) == 0) part[tid >> 5] = v;
    }
    int i = b * 1024 + tid;
    int v = (i < n) ? g_degi[i] : 0;
    int incl = v;
    #pragma unroll
    for (int off = 1; off < 32; off <<= 1) {
        int t = __shfl_up_sync(0xffffffffu, incl, off);
        if (lane >= off) incl += t;
    }
    if (lane == 31) wsum[w] = incl;
    __syncthreads();
    if (w == 0) {
        int t = wsum[lane];
        #pragma unroll
        for (int off = 1; off < 32; off <<= 1) {
            int u = __shfl_up_sync(0xffffffffu, t, off);
            if (lane >= off) t += u;
        }
        wsum[lane] = t;
    }
    __syncthreads();
    int boff = part[0] + part[1];
    int excl = boff + ((w == 0) ? 0 : wsum[w - 1]) + incl - v;
    if (i < n) {
        g_row[i]    = excl;
        g_cursor[i] = excl;
        g_inv[i]    = 1.0f / fmaxf((float)v, 1.0f);
        if (i == n - 1) g_row[n] = excl + v;
    }
}

__global__ void fill_kernel(const void* __restrict__ ei, int E) {
    int e = blockIdx.x * blockDim.x + threadIdx.x;
    if (e < E) {
        int is64 = g_is64;
        int src = load_edge(ei, e, is64);
        int dst = load_edge(ei, E + e, is64);
        int pos = atomicAdd(&g_cursor[dst], 1);
        g_csr[pos] = src;
    }
}

// ---------------- gather-based mean aggregation (fp16 input, fp32 accum) ----
// lane covers cols [4*lane, 4*lane+4): one uint2 = 4 halves per neighbor row.
__global__ void gather_mean_kernel(const __half* __restrict__ x,
                                   float* __restrict__ meanout, int n) {
    int gt = blockIdx.x * blockDim.x + threadIdx.x;
    int warp = gt >> 5;
    int lane = gt & 31;
    if (warp >= n) return;
    int start = g_row[warp];
    int end   = g_row[warp + 1];
    float4 a0 = make_float4(0.f, 0.f, 0.f, 0.f);
    float4 a1 = make_float4(0.f, 0.f, 0.f, 0.f);
    for (int j0 = start; j0 < end; j0 += 32) {
        int cnt = min(32, end - j0);
        int myidx = (lane < cnt) ? g_csr[j0 + lane] : 0;
        int j = 0;
        for (; j + 4 <= cnt; j += 4) {
            int s0 = __shfl_sync(0xffffffffu, myidx, j + 0);
            int s1 = __shfl_sync(0xffffffffu, myidx, j + 1);
            int s2 = __shfl_sync(0xffffffffu, myidx, j + 2);
            int s3 = __shfl_sync(0xffffffffu, myidx, j + 3);
            uint2 u0 = __ldg((const uint2*)(x + (size_t)s0 * 128) + lane);
            uint2 u1 = __ldg((const uint2*)(x + (size_t)s1 * 128) + lane);
            uint2 u2 = __ldg((const uint2*)(x + (size_t)s2 * 128) + lane);
            uint2 u3 = __ldg((const uint2*)(x + (size_t)s3 * 128) + lane);
            float2 f;
            f = __half22float2(*(__half2*)&u0.x); a0.x += f.x; a0.y += f.y;
            f = __half22float2(*(__half2*)&u0.y); a0.z += f.x; a0.w += f.y;
            f = __half22float2(*(__half2*)&u1.x); a1.x += f.x; a1.y += f.y;
            f = __half22float2(*(__half2*)&u1.y); a1.z += f.x; a1.w += f.y;
            f = __half22float2(*(__half2*)&u2.x); a0.x += f.x; a0.y += f.y;
            f = __half22float2(*(__half2*)&u2.y); a0.z += f.x; a0.w += f.y;
            f = __half22float2(*(__half2*)&u3.x); a1.x += f.x; a1.y += f.y;
            f = __half22float2(*(__half2*)&u3.y); a1.z += f.x; a1.w += f.y;
        }
        for (; j < cnt; j++) {
            int s0 = __shfl_sync(0xffffffffu, myidx, j);
            uint2 u0 = __ldg((const uint2*)(x + (size_t)s0 * 128) + lane);
            float2 f;
            f = __half22float2(*(__half2*)&u0.x); a0.x += f.x; a0.y += f.y;
            f = __half22float2(*(__half2*)&u0.y); a0.z += f.x; a0.w += f.y;
        }
    }
    float inv = g_inv[warp];
    float4 r;
    r.x = (a0.x + a1.x) * inv;
    r.y = (a0.y + a1.y) * inv;
    r.z = (a0.z + a1.z) * inv;
    r.w = (a0.w + a1.w) * inv;
    ((float4*)meanout)[warp * 32 + lane] = r;
}

// ---------------- W^T prep: hi/lo bf16 split, row-major [OUT][128] ----------
__global__ void prep_w_kernel(const float* w1n, const float* w1r,
                              const float* w2n, const float* w2r,
                              const float* wr1, const float* wfn,
                              const float* wfr, const float* wr2) {
    int m = blockIdx.x;
    const float* W;
    switch (m) {
        case 0: W = w1n; break; case 1: W = w1r; break;
        case 2: W = w2n; break; case 3: W = w2r; break;
        case 4: W = wr1; break; case 5: W = wfn; break;
        case 6: W = wfr; break; default: W = wr2; break;
    }
    int OUT = (m < 5) ? 128 : 64;
    unsigned short* hi = (unsigned short*)&g_wt[m][0];
    unsigned short* lo = (unsigned short*)((char*)&g_wt[m][0] + 32768);
    for (int idx = threadIdx.x; idx < 128 * OUT; idx += blockDim.x) {
        int k = idx / OUT, nn = idx % OUT;       // W row-major [128][OUT]
        float v = W[idx];
        __nv_bfloat16 h = __float2bfloat16(v);
        __nv_bfloat16 l = __float2bfloat16(v - __bfloat162float(h));
        hi[nn * 128 + k] = *reinterpret_cast<unsigned short*>(&h);
        lo[nn * 128 + k] = *reinterpret_cast<unsigned short*>(&l);
    }
}

// ---------------- MMA layer kernel (mma.sync bf16, split-compensated) --------
// 256 threads = 8 warps; 128 rows/CTA, warp owns 16 rows x full OUT.
// W hi/lo double-buffered via cp.async; A register-pipelined one stream ahead.
// HOUT: also emit fp16 copy of the output (consumed by the next gather).
// smem: biasA(512) biasB(512) | Ahi(32K) | Alo(32K) | Wbuf0(2*WTILE) | Wbuf1(2*WTILE)
template<int N, int NS, bool RELU_MID, bool RELU_END, bool HASB2, bool SIG, bool HOUT>
__global__ void __launch_bounds__(256, 1)
layer_kernel(const float* __restrict__ A0, const float* __restrict__ A1,
             const float* __restrict__ A2,
             const uint4* __restrict__ T0, const uint4* __restrict__ T1,
             const uint4* __restrict__ T2,
             const float* __restrict__ biasA, const float* __restrict__ biasB,
             float* __restrict__ out, __half* __restrict__ outh, int n) {
    extern __shared__ unsigned char smem[];
    const int WTILE = N * 256;
    float* sBiasA = (float*)smem;
    float* sBiasB = (float*)(smem + 512);
    unsigned char* sAhi = smem + 1024;
    unsigned char* sAlo = sAhi + 32768;
    unsigned char* sW0  = sAlo + 32768;
    unsigned char* sW1  = sW0 + 2 * WTILE;
    uint32_t uAhi = smem_u32(sAhi), uAlo = smem_u32(sAlo);
    uint32_t uW[2] = { smem_u32(sW0), smem_u32(sW1) };

    int tid = threadIdx.x, wid = tid >> 5, lane = tid & 31;
    int tileBase = blockIdx.x * 128;

    if (tid < N) {
        sBiasA[tid] = biasA[tid];
        if (HASB2) sBiasB[tid] = biasB[tid];
    }

    const float* As[3] = {A0, A1, A2};
    const uint4* Ts[3] = {T0, T1, T2};

    float acc[N / 8][4];
    #pragma unroll
    for (int nc = 0; nc < N / 8; nc++)
        #pragma unroll
        for (int j = 0; j < 4; j++) acc[nc][j] = 0.f;

    int arow = (wid << 4) + (lane & 15);
    uint32_t aoffBase = (uint32_t)arow * 256 + ((lane >> 4) << 4);
    uint32_t aswz = (uint32_t)(arow & 7) << 4;
    int brow_loc = (lane & 7) + ((lane >> 4) << 3);
    uint32_t bkoff = (lane & 8) ? 16u : 0u;
    uint32_t bswz = (uint32_t)(brow_loc & 7) << 4;

    auto stageW = [&](int s, int b) {
        const uint4* srcH = Ts[s];
        const uint4* srcL = Ts[s] + 2048;
        uint32_t base = uW[b];
        #pragma unroll
        for (int u0 = 0; u0 < N * 16; u0 += 256) {
            int u = u0 + tid;
            int nr = u >> 4;
            uint32_t off = ((uint32_t)u * 16) ^ ((uint32_t)(nr & 7) << 4);
            cp_async16(base + off, srcH + u);
            cp_async16(base + WTILE + off, srcL + u);
        }
    };

    float4 aReg[16];
    auto loadA = [&](const float* A) {
        #pragma unroll
        for (int i = 0; i < 8; i++) {
            int u = (wid << 8) + (i << 5) + lane;
            int row = u >> 4, kc = u & 15;
            int grow = tileBase + row;
            grow = (grow < n) ? grow : (n - 1);
            const float4* src = (const float4*)(A + (size_t)grow * 128 + kc * 8);
            aReg[2 * i]     = __ldg(src);
            aReg[2 * i + 1] = __ldg(src + 1);
        }
    };
    auto storeA = [&]() {
        #pragma unroll
        for (int i = 0; i < 8; i++) {
            int u = (wid << 8) + (i << 5) + lane;
            int row = u >> 4;
            float4 v0 = aReg[2 * i], v1 = aReg[2 * i + 1];
            float h[8], l[8];
            #pragma unroll
            for (int j = 0; j < 8; j++) {
                float x = (j < 4) ? (&v0.x)[j] : (&v1.x)[j - 4];
                __nv_bfloat16 hb = __float2bfloat16(x);
                h[j] = __bfloat162float(hb);
                l[j] = x - h[j];
            }
            uint4 ph, pl;
            ph.x = pack2bf(h[0], h[1]); ph.y = pack2bf(h[2], h[3]);
            ph.z = pack2bf(h[4], h[5]); ph.w = pack2bf(h[6], h[7]);
            pl.x = pack2bf(l[0], l[1]); pl.y = pack2bf(l[2], l[3]);
            pl.z = pack2bf(l[4], l[5]); pl.w = pack2bf(l[6], l[7]);
            uint32_t off = ((uint32_t)u * 16) ^ ((uint32_t)(row & 7) << 4);
            *(uint4*)(sAhi + off) = ph;
            *(uint4*)(sAlo + off) = pl;
        }
        __syncwarp();
    };

    stageW(0, 0);
    CP_COMMIT();
    loadA(As[0]);

    #pragma unroll
    for (int s = 0; s < NS; s++) {
        if (s + 1 < NS) { stageW(s + 1, (s + 1) & 1); CP_COMMIT(); }

        storeA();

        if (s + 1 < NS) CP_WAIT(1); else CP_WAIT(0);
        __syncthreads();

        if (s + 1 < NS) loadA(As[s + 1]);

        uint32_t uWhi = uW[s & 1];
        uint32_t uWlo = uWhi + WTILE;

        #pragma unroll
        for (int kc = 0; kc < 8; kc++) {
            uint32_t ah[4], al[4];
            uint32_t aoff = ((aoffBase + kc * 32) ^ aswz);
            ldsm_x4(uAhi + aoff, ah[0], ah[1], ah[2], ah[3]);
            ldsm_x4(uAlo + aoff, al[0], al[1], al[2], al[3]);
            #pragma unroll
            for (int np = 0; np < N / 16; np++) {
                uint32_t boff = (((uint32_t)(np * 16 + brow_loc) * 256
                                  + kc * 32 + bkoff) ^ bswz);
                uint32_t bh0, bh1, bh2, bh3, bl0, bl1, bl2, bl3;
                ldsm_x4(uWhi + boff, bh0, bh1, bh2, bh3);
                ldsm_x4(uWlo + boff, bl0, bl1, bl2, bl3);
                mma_bf16(acc[2 * np],     ah, bh0, bh1);
                mma_bf16(acc[2 * np],     ah, bl0, bl1);
                mma_bf16(acc[2 * np],     al, bh0, bh1);
                mma_bf16(acc[2 * np + 1], ah, bh2, bh3);
                mma_bf16(acc[2 * np + 1], ah, bl2, bl3);
                mma_bf16(acc[2 * np + 1], al, bh2, bh3);
            }
        }

        if (RELU_MID && s == 1) {
            #pragma unroll
            for (int nc = 0; nc < N / 8; nc++) {
                int c = nc * 8 + (lane & 3) * 2;
                float b0 = sBiasA[c], b1 = sBiasA[c + 1];
                acc[nc][0] = fmaxf(acc[nc][0] + b0, 0.f);
                acc[nc][1] = fmaxf(acc[nc][1] + b1, 0.f);
                acc[nc][2] = fmaxf(acc[nc][2] + b0, 0.f);
                acc[nc][3] = fmaxf(acc[nc][3] + b1, 0.f);
            }
        }

        if (s + 1 < NS) __syncthreads();
    }

    // epilogue
    int r0 = tileBase + (wid << 4) + (lane >> 2);
    int r1 = r0 + 8;
    #pragma unroll
    for (int nc = 0; nc < N / 8; nc++) {
        int c = nc * 8 + (lane & 3) * 2;
        float bA0 = RELU_MID ? 0.f : sBiasA[c];
        float bA1 = RELU_MID ? 0.f : sBiasA[c + 1];
        float bB0 = HASB2 ? sBiasB[c] : 0.f;
        float bB1 = HASB2 ? sBiasB[c + 1] : 0.f;
        #pragma unroll
        for (int half = 0; half < 2; half++) {
            int row = half ? r1 : r0;
            if (row >= n) continue;
            float v0 = acc[nc][2 * half]     + bA0;
            float v1 = acc[nc][2 * half + 1] + bA1;
            if (RELU_END) { v0 = fmaxf(v0, 0.f); v1 = fmaxf(v1, 0.f); }
            v0 += bB0; v1 += bB1;
            if (SIG && c < 8) {
                v0 = 1.0f / (1.0f + expf(-v0));
                v1 = 1.0f / (1.0f + expf(-v1));
            }
            *(float2*)(out + (size_t)row * N + c) = make_float2(v0, v1);
            if (HOUT) {
                __half2 hv = __floats2half2_rn(v0, v1);
                *(__half2*)(outh + (size_t)row * N + c) = hv;
            }
        }
    }
}

// ---------------- launch ----------------------------------------------------
extern "C" void kernel_launch(void* const* d_in, const int* in_sizes, int n_in,
                              void* d_out, int out_size) {
    const float* z   = (const float*)d_in[0];
    const void*  ei  = d_in[1];
    const float* w1n = (const float*)d_in[2];
    const float* w1r = (const float*)d_in[3];
    const float* b1  = (const float*)d_in[4];
    const float* w2n = (const float*)d_in[5];
    const float* w2r = (const float*)d_in[6];
    const float* b2  = (const float*)d_in[7];
    const float* wfn = (const float*)d_in[8];
    const float* wfr = (const float*)d_in[9];
    const float* bf  = (const float*)d_in[10];
    const float* wr1 = (const float*)d_in[11];
    const float* br1 = (const float*)d_in[12];
    const float* wr2 = (const float*)d_in[13];
    const float* br2 = (const float*)d_in[14];

    int n = in_sizes[0] / 128;
    int E = in_sizes[1] / 2;
    float* out = (float*)d_out;

    float *p_mean, *p_h1, *p_h2;
    __half *p_zh, *p_h1h, *p_h2h;
    uint4* p_wt;
    cudaGetSymbolAddress((void**)&p_mean, g_mean);
    cudaGetSymbolAddress((void**)&p_h1, g_h1);
    cudaGetSymbolAddress((void**)&p_h2, g_h2);
    cudaGetSymbolAddress((void**)&p_zh, g_zh);
    cudaGetSymbolAddress((void**)&p_h1h, g_h1h);
    cudaGetSymbolAddress((void**)&p_h2h, g_h2h);
    cudaGetSymbolAddress((void**)&p_wt, g_wt);

    const int smemN128 = 1024 + 65536 + 4 * 128 * 256;   // 193 KB
    const int smemN64  = 1024 + 65536 + 4 * 64 * 256;    // 129 KB
    cudaFuncSetAttribute(layer_kernel<128, 2, false, true, false, false, true>,
                         cudaFuncAttributeMaxDynamicSharedMemorySize, smemN128);
    cudaFuncSetAttribute(layer_kernel<128, 3, true, false, true, false, true>,
                         cudaFuncAttributeMaxDynamicSharedMemorySize, smemN128);
    cudaFuncSetAttribute(layer_kernel<64, 3, false, false, true, true, false>,
                         cudaFuncAttributeMaxDynamicSharedMemorySize, smemN64);

    int nb = (n + 1023) / 1024;
    int gblocks = (n * 32 + 255) / 256;   // gather: 1 warp/node
    int mblocks = (n + 127) / 128;        // layer kernels: 128 rows/CTA
    int hblocks = ((n * 32) + 255) / 256; // tohalf: n*128/4 threads
    #define WT(i) (p_wt + (size_t)(i) * 4096)

    // weight prep + z fp16 copy + CSR build (proven R7 path)
    prep_w_kernel<<<8, 256>>>(w1n, w1r, w2n, w2r, wr1, wfn, wfr, wr2);
    tohalf_kernel<<<hblocks, 256>>>(z, p_zh, n * 32);
    init_kernel<<<(n + 255) / 256, 256>>>((const unsigned long long*)ei, n);
    hist_kernel<<<(E + 255) / 256, 256>>>(ei, E);
    bsum_kernel<<<nb, 256>>>(n);
    scan2_kernel<<<nb, 1024>>>(n);
    fill_kernel<<<(E + 255) / 256, 256>>>(ei, E);

    // layer 1: h1 = relu(mean(z) @ w1n + z @ w1r + b1)       [+ fp16 copy]
    gather_mean_kernel<<<gblocks, 256>>>(p_zh, p_mean, n);
    layer_kernel<128, 2, false, true, false, false, true><<<mblocks, 256, smemN128>>>(
        p_mean, z, nullptr, WT(0), WT(1), nullptr, b1, nullptr, p_h1, p_h1h, n);

    // layer 2: h2 = relu(mean(h1) @ w2n + h1 @ w2r + b2) + z @ wr1 + br1
    gather_mean_kernel<<<gblocks, 256>>>(p_h1h, p_mean, n);
    layer_kernel<128, 3, true, false, true, false, true><<<mblocks, 256, smemN128>>>(
        p_mean, p_h1, z, WT(2), WT(3), WT(4), b2, br1, p_h2, p_h2h, n);

    // layer 3: out = mean(h2) @ wfn + h2 @ wfr + z @ wr2 + bf + br2; sigmoid[:8]
    gather_mean_kernel<<<gblocks, 256>>>(p_h2h, p_mean, n);
    layer_kernel<64, 3, false, false, true, true, false><<<mblocks, 256, smemN64>>>(
        p_mean, p_h2, z, WT(5), WT(6), WT(7), bf, br2, out, nullptr, n);
}

// round 16
// speedup vs baseline: 1.6729x; 1.0360x over previous
#include <cuda_runtime.h>
#include <cuda_bf16.h>
#include <cstdint>
#include <math.h>

#define NMAX 50000
#define EMAX 800000

// ---------------- device scratch ------------------------------------------
__device__ int   g_is64;
__device__ int   g_degi[NMAX];
__device__ int   g_row[NMAX + 1];
__device__ float g_inv[NMAX];
__device__ int   g_rank[EMAX];
__device__ int   g_csr[EMAX];
__device__ int   g_bsum[64];
__device__ float g_mean[(size_t)NMAX * 128];
__device__ float g_h1[(size_t)NMAX * 128];
__device__ float g_h2[(size_t)NMAX * 128];
// W^T bf16 images per matrix slot: hi at +0, lo at +32768 bytes (row-major [OUT][128])
__device__ uint4 g_wt[8][4096];

// ---------------- helpers ----------------------------------------------------
__device__ __forceinline__ uint32_t smem_u32(const void* p) {
    uint32_t a;
    asm("{ .reg .u64 t; cvta.to.shared.u64 t, %1; cvt.u32.u64 %0, t; }"
        : "=r"(a) : "l"(p));
    return a;
}
__device__ __forceinline__ uint32_t pack2bf(float x, float y) {
    __nv_bfloat162 t = __floats2bfloat162_rn(x, y);
    return *reinterpret_cast<uint32_t*>(&t);
}
__device__ __forceinline__ void ldsm_x4(uint32_t addr, uint32_t& r0, uint32_t& r1,
                                        uint32_t& r2, uint32_t& r3) {
    asm volatile("ldmatrix.sync.aligned.m8n8.x4.shared.b16 {%0,%1,%2,%3}, [%4];"
                 : "=r"(r0), "=r"(r1), "=r"(r2), "=r"(r3) : "r"(addr));
}
__device__ __forceinline__ void mma_bf16(float (&c)[4], const uint32_t (&a)[4],
                                         uint32_t b0, uint32_t b1) {
    asm volatile(
        "mma.sync.aligned.m16n8k16.row.col.f32.bf16.bf16.f32 "
        "{%0,%1,%2,%3}, {%4,%5,%6,%7}, {%8,%9}, {%0,%1,%2,%3};"
        : "+f"(c[0]), "+f"(c[1]), "+f"(c[2]), "+f"(c[3])
        : "r"(a[0]), "r"(a[1]), "r"(a[2]), "r"(a[3]), "r"(b0), "r"(b1));
}
__device__ __forceinline__ void cp_async16(uint32_t dst, const void* src) {
    asm volatile("cp.async.cg.shared.global [%0], [%1], 16;"
                 :: "r"(dst), "l"(src) : "memory");
}
#define CP_COMMIT() asm volatile("cp.async.commit_group;" ::: "memory")
#define CP_WAIT(n)  asm volatile("cp.async.wait_group %0;" :: "n"(n) : "memory")

// ---------------- init: zero degrees + index-width detect -------------------
// jax "int64" silently becomes int32 when x64 is disabled; detect on-device.
__global__ void init_kernel(const unsigned long long* __restrict__ p, int n) {
    int i = blockIdx.x * blockDim.x + threadIdx.x;
    if (i < n) g_degi[i] = 0;
    if (i == 0) {
        int is64 = 1;
        #pragma unroll
        for (int k = 0; k < 8; k++)
            if (p[k] >= 50000ULL) is64 = 0;
        g_is64 = is64;
    }
}

__device__ __forceinline__ int load_edge(const void* ei, int pos, int is64) {
    if (is64) return (int)((const long long*)ei)[pos];
    return ((const int*)ei)[pos];
}

// hist: count degrees AND record each edge's rank among same-dst edges
__global__ void hist_kernel(const void* __restrict__ ei, int E) {
    int e = blockIdx.x * blockDim.x + threadIdx.x;
    if (e < E) {
        int dst = load_edge(ei, E + e, g_is64);
        g_rank[e] = atomicAdd(&g_degi[dst], 1);
    }
}

__global__ void bsum_kernel(int n) {
    __shared__ int ws[8];
    int b = blockIdx.x, tid = threadIdx.x;
    int v = 0;
    int base = b * 1024;
    for (int i = tid; i < 1024; i += 256) {
        int idx = base + i;
        if (idx < n) v += g_degi[idx];
    }
    #pragma unroll
    for (int off = 16; off; off >>= 1) v += __shfl_down_sync(0xffffffffu, v, off);
    if ((tid & 31) == 0) ws[tid >> 5] = v;
    __syncthreads();
    if (tid == 0) {
        int s = 0;
        #pragma unroll
        for (int k = 0; k < 8; k++) s += ws[k];
        g_bsum[b] = s;
    }
}

__global__ void scan2_kernel(int n) {
    __shared__ int wsum[32];
    __shared__ int part[2];
    int b = blockIdx.x, tid = threadIdx.x;
    int lane = tid & 31, w = tid >> 5;
    if (tid < 64) {
        int v = (tid < b) ? g_bsum[tid] : 0;
        #pragma unroll
        for (int off = 16; off; off >>= 1) v += __shfl_down_sync(0xffffffffu, v, off);
        if ((tid & 31) == 0) part[tid >> 5] = v;
    }
    int i = b * 1024 + tid;
    int v = (i < n) ? g_degi[i] : 0;
    int incl = v;
    #pragma unroll
    for (int off = 1; off < 32; off <<= 1) {
        int t = __shfl_up_sync(0xffffffffu, incl, off);
        if (lane >= off) incl += t;
    }
    if (lane == 31) wsum[w] = incl;
    __syncthreads();
    if (w == 0) {
        int t = wsum[lane];
        #pragma unroll
        for (int off = 1; off < 32; off <<= 1) {
            int u = __shfl_up_sync(0xffffffffu, t, off);
            if (lane >= off) t += u;
        }
        wsum[lane] = t;
    }
    __syncthreads();
    int boff = part[0] + part[1];
    int excl = boff + ((w == 0) ? 0 : wsum[w - 1]) + incl - v;
    if (i < n) {
        g_row[i] = excl;
        g_inv[i] = 1.0f / fmaxf((float)v, 1.0f);
        if (i == n - 1) g_row[n] = excl + v;
    }
}

// fill: atomic-free scatter via precomputed ranks
__global__ void fill_kernel(const void* __restrict__ ei, int E) {
    int e = blockIdx.x * blockDim.x + threadIdx.x;
    if (e < E) {
        int is64 = g_is64;
        int src = load_edge(ei, e, is64);
        int dst = load_edge(ei, E + e, is64);
        g_csr[g_row[dst] + g_rank[e]] = src;
    }
}

// ---------------- gather-based mean aggregation (atomic-free) ---------------
__global__ void gather_mean_kernel(const float* __restrict__ x,
                                   float* __restrict__ meanout, int n) {
    int gt = blockIdx.x * blockDim.x + threadIdx.x;
    int warp = gt >> 5;
    int lane = gt & 31;
    if (warp >= n) return;
    int start = g_row[warp];
    int end   = g_row[warp + 1];
    const float4* __restrict__ x4 = (const float4*)x;
    float4 a0 = make_float4(0.f, 0.f, 0.f, 0.f);
    float4 a1 = make_float4(0.f, 0.f, 0.f, 0.f);
    for (int j0 = start; j0 < end; j0 += 32) {
        int cnt = min(32, end - j0);
        int myidx = (lane < cnt) ? g_csr[j0 + lane] : 0;
        int j = 0;
        for (; j + 4 <= cnt; j += 4) {
            int s0 = __shfl_sync(0xffffffffu, myidx, j + 0);
            int s1 = __shfl_sync(0xffffffffu, myidx, j + 1);
            int s2 = __shfl_sync(0xffffffffu, myidx, j + 2);
            int s3 = __shfl_sync(0xffffffffu, myidx, j + 3);
            float4 v0 = __ldg(&x4[s0 * 32 + lane]);
            float4 v1 = __ldg(&x4[s1 * 32 + lane]);
            float4 v2 = __ldg(&x4[s2 * 32 + lane]);
            float4 v3 = __ldg(&x4[s3 * 32 + lane]);
            a0.x += v0.x; a0.y += v0.y; a0.z += v0.z; a0.w += v0.w;
            a1.x += v1.x; a1.y += v1.y; a1.z += v1.z; a1.w += v1.w;
            a0.x += v2.x; a0.y += v2.y; a0.z += v2.z; a0.w += v2.w;
            a1.x += v3.x; a1.y += v3.y; a1.z += v3.z; a1.w += v3.w;
        }
        for (; j < cnt; j++) {
            int s0 = __shfl_sync(0xffffffffu, myidx, j);
            float4 v0 = __ldg(&x4[s0 * 32 + lane]);
            a0.x += v0.x; a0.y += v0.y; a0.z += v0.z; a0.w += v0.w;
        }
    }
    float inv = g_inv[warp];
    float4 r;
    r.x = (a0.x + a1.x) * inv;
    r.y = (a0.y + a1.y) * inv;
    r.z = (a0.z + a1.z) * inv;
    r.w = (a0.w + a1.w) * inv;
    ((float4*)meanout)[warp * 32 + lane] = r;
}

// ---------------- W^T prep: hi/lo bf16 split, row-major [OUT][128] ----------
__global__ void prep_w_kernel(const float* w1n, const float* w1r,
                              const float* w2n, const float* w2r,
                              const float* wr1, const float* wfn,
                              const float* wfr, const float* wr2) {
    int m = blockIdx.x;
    const float* W;
    switch (m) {
        case 0: W = w1n; break; case 1: W = w1r; break;
        case 2: W = w2n; break; case 3: W = w2r; break;
        case 4: W = wr1; break; case 5: W = wfn; break;
        case 6: W = wfr; break; default: W = wr2; break;
    }
    int OUT = (m < 5) ? 128 : 64;
    unsigned short* hi = (unsigned short*)&g_wt[m][0];
    unsigned short* lo = (unsigned short*)((char*)&g_wt[m][0] + 32768);
    for (int idx = threadIdx.x; idx < 128 * OUT; idx += blockDim.x) {
        int k = idx / OUT, nn = idx % OUT;       // W row-major [128][OUT]
        float v = W[idx];
        __nv_bfloat16 h = __float2bfloat16(v);
        __nv_bfloat16 l = __float2bfloat16(v - __bfloat162float(h));
        hi[nn * 128 + k] = *reinterpret_cast<unsigned short*>(&h);
        lo[nn * 128 + k] = *reinterpret_cast<unsigned short*>(&l);
    }
}

// ---------------- MMA layer kernel (mma.sync bf16, split-compensated) --------
// 256 threads = 8 warps; 128 rows/CTA, warp owns 16 rows x full OUT.
// W hi/lo double-buffered via cp.async; A register-pipelined one stream ahead.
// smem: biasA(512) biasB(512) | Ahi(32K) | Alo(32K) | Wbuf0(2*WTILE) | Wbuf1(2*WTILE)
template<int N, int NS, bool RELU_MID, bool RELU_END, bool HASB2, bool SIG>
__global__ void __launch_bounds__(256, 1)
layer_kernel(const float* __restrict__ A0, const float* __restrict__ A1,
             const float* __restrict__ A2,
             const uint4* __restrict__ T0, const uint4* __restrict__ T1,
             const uint4* __restrict__ T2,
             const float* __restrict__ biasA, const float* __restrict__ biasB,
             float* __restrict__ out, int n) {
    extern __shared__ unsigned char smem[];
    const int WTILE = N * 256;
    float* sBiasA = (float*)smem;
    float* sBiasB = (float*)(smem + 512);
    unsigned char* sAhi = smem + 1024;
    unsigned char* sAlo = sAhi + 32768;
    unsigned char* sW0  = sAlo + 32768;
    unsigned char* sW1  = sW0 + 2 * WTILE;
    uint32_t uAhi = smem_u32(sAhi), uAlo = smem_u32(sAlo);
    uint32_t uW[2] = { smem_u32(sW0), smem_u32(sW1) };

    int tid = threadIdx.x, wid = tid >> 5, lane = tid & 31;
    int tileBase = blockIdx.x * 128;

    if (tid < N) {
        sBiasA[tid] = biasA[tid];
        if (HASB2) sBiasB[tid] = biasB[tid];
    }

    const float* As[3] = {A0, A1, A2};
    const uint4* Ts[3] = {T0, T1, T2};

    float acc[N / 8][4];
    #pragma unroll
    for (int nc = 0; nc < N / 8; nc++)
        #pragma unroll
        for (int j = 0; j < 4; j++) acc[nc][j] = 0.f;

    int arow = (wid << 4) + (lane & 15);
    uint32_t aoffBase = (uint32_t)arow * 256 + ((lane >> 4) << 4);
    uint32_t aswz = (uint32_t)(arow & 7) << 4;
    int brow_loc = (lane & 7) + ((lane >> 4) << 3);
    uint32_t bkoff = (lane & 8) ? 16u : 0u;
    uint32_t bswz = (uint32_t)(brow_loc & 7) << 4;

    auto stageW = [&](int s, int b) {
        const uint4* srcH = Ts[s];
        const uint4* srcL = Ts[s] + 2048;
        uint32_t base = uW[b];
        #pragma unroll
        for (int u0 = 0; u0 < N * 16; u0 += 256) {
            int u = u0 + tid;
            int nr = u >> 4;
            uint32_t off = ((uint32_t)u * 16) ^ ((uint32_t)(nr & 7) << 4);
            cp_async16(base + off, srcH + u);
            cp_async16(base + WTILE + off, srcL + u);
        }
    };

    float4 aReg[16];
    auto loadA = [&](const float* A) {
        #pragma unroll
        for (int i = 0; i < 8; i++) {
            int u = (wid << 8) + (i << 5) + lane;
            int row = u >> 4, kc = u & 15;
            int grow = tileBase + row;
            grow = (grow < n) ? grow : (n - 1);
            const float4* src = (const float4*)(A + (size_t)grow * 128 + kc * 8);
            aReg[2 * i]     = __ldg(src);
            aReg[2 * i + 1] = __ldg(src + 1);
        }
    };
    auto storeA = [&]() {
        #pragma unroll
        for (int i = 0; i < 8; i++) {
            int u = (wid << 8) + (i << 5) + lane;
            int row = u >> 4;
            float4 v0 = aReg[2 * i], v1 = aReg[2 * i + 1];
            float h[8], l[8];
            #pragma unroll
            for (int j = 0; j < 8; j++) {
                float x = (j < 4) ? (&v0.x)[j] : (&v1.x)[j - 4];
                __nv_bfloat16 hb = __float2bfloat16(x);
                h[j] = __bfloat162float(hb);
                l[j] = x - h[j];
            }
            uint4 ph, pl;
            ph.x = pack2bf(h[0], h[1]); ph.y = pack2bf(h[2], h[3]);
            ph.z = pack2bf(h[4], h[5]); ph.w = pack2bf(h[6], h[7]);
            pl.x = pack2bf(l[0], l[1]); pl.y = pack2bf(l[2], l[3]);
            pl.z = pack2bf(l[4], l[5]); pl.w = pack2bf(l[6], l[7]);
            uint32_t off = ((uint32_t)u * 16) ^ ((uint32_t)(row & 7) << 4);
            *(uint4*)(sAhi + off) = ph;
            *(uint4*)(sAlo + off) = pl;
        }
        __syncwarp();
    };

    stageW(0, 0);
    CP_COMMIT();
    loadA(As[0]);

    #pragma unroll
    for (int s = 0; s < NS; s++) {
        if (s + 1 < NS) { stageW(s + 1, (s + 1) & 1); CP_COMMIT(); }

        storeA();

        if (s + 1 < NS) CP_WAIT(1); else CP_WAIT(0);
        __syncthreads();

        if (s + 1 < NS) loadA(As[s + 1]);

        uint32_t uWhi = uW[s & 1];
        uint32_t uWlo = uWhi + WTILE;

        #pragma unroll
        for (int kc = 0; kc < 8; kc++) {
            uint32_t ah[4], al[4];
            uint32_t aoff = ((aoffBase + kc * 32) ^ aswz);
            ldsm_x4(uAhi + aoff, ah[0], ah[1], ah[2], ah[3]);
            ldsm_x4(uAlo + aoff, al[0], al[1], al[2], al[3]);
            #pragma unroll
            for (int np = 0; np < N / 16; np++) {
                uint32_t boff = (((uint32_t)(np * 16 + brow_loc) * 256
                                  + kc * 32 + bkoff) ^ bswz);
                uint32_t bh0, bh1, bh2, bh3, bl0, bl1, bl2, bl3;
                ldsm_x4(uWhi + boff, bh0, bh1, bh2, bh3);
                ldsm_x4(uWlo + boff, bl0, bl1, bl2, bl3);
                mma_bf16(acc[2 * np],     ah, bh0, bh1);
                mma_bf16(acc[2 * np],     ah, bl0, bl1);
                mma_bf16(acc[2 * np],     al, bh0, bh1);
                mma_bf16(acc[2 * np + 1], ah, bh2, bh3);
                mma_bf16(acc[2 * np + 1], ah, bl2, bl3);
                mma_bf16(acc[2 * np + 1], al, bh2, bh3);
            }
        }

        if (RELU_MID && s == 1) {
            #pragma unroll
            for (int nc = 0; nc < N / 8; nc++) {
                int c = nc * 8 + (lane & 3) * 2;
                float b0 = sBiasA[c], b1 = sBiasA[c + 1];
                acc[nc][0] = fmaxf(acc[nc][0] + b0, 0.f);
                acc[nc][1] = fmaxf(acc[nc][1] + b1, 0.f);
                acc[nc][2] = fmaxf(acc[nc][2] + b0, 0.f);
                acc[nc][3] = fmaxf(acc[nc][3] + b1, 0.f);
            }
        }

        if (s + 1 < NS) __syncthreads();
    }

    // epilogue
    int r0 = tileBase + (wid << 4) + (lane >> 2);
    int r1 = r0 + 8;
    #pragma unroll
    for (int nc = 0; nc < N / 8; nc++) {
        int c = nc * 8 + (lane & 3) * 2;
        float bA0 = RELU_MID ? 0.f : sBiasA[c];
        float bA1 = RELU_MID ? 0.f : sBiasA[c + 1];
        float bB0 = HASB2 ? sBiasB[c] : 0.f;
        float bB1 = HASB2 ? sBiasB[c + 1] : 0.f;
        #pragma unroll
        for (int half = 0; half < 2; half++) {
            int row = half ? r1 : r0;
            if (row >= n) continue;
            float v0 = acc[nc][2 * half]     + bA0;
            float v1 = acc[nc][2 * half + 1] + bA1;
            if (RELU_END) { v0 = fmaxf(v0, 0.f); v1 = fmaxf(v1, 0.f); }
            v0 += bB0; v1 += bB1;
            if (SIG && c < 8) {
                v0 = 1.0f / (1.0f + expf(-v0));
                v1 = 1.0f / (1.0f + expf(-v1));
            }
            *(float2*)(out + (size_t)row * N + c) = make_float2(v0, v1);
        }
    }
}

// ---------------- launch ----------------------------------------------------
extern "C" void kernel_launch(void* const* d_in, const int* in_sizes, int n_in,
                              void* d_out, int out_size) {
    const float* z   = (const float*)d_in[0];
    const void*  ei  = d_in[1];
    const float* w1n = (const float*)d_in[2];
    const float* w1r = (const float*)d_in[3];
    const float* b1  = (const float*)d_in[4];
    const float* w2n = (const float*)d_in[5];
    const float* w2r = (const float*)d_in[6];
    const float* b2  = (const float*)d_in[7];
    const float* wfn = (const float*)d_in[8];
    const float* wfr = (const float*)d_in[9];
    const float* bf  = (const float*)d_in[10];
    const float* wr1 = (const float*)d_in[11];
    const float* br1 = (const float*)d_in[12];
    const float* wr2 = (const float*)d_in[13];
    const float* br2 = (const float*)d_in[14];

    int n = in_sizes[0] / 128;
    int E = in_sizes[1] / 2;
    float* out = (float*)d_out;

    float *p_mean, *p_h1, *p_h2;
    uint4* p_wt;
    cudaGetSymbolAddress((void**)&p_mean, g_mean);
    cudaGetSymbolAddress((void**)&p_h1, g_h1);
    cudaGetSymbolAddress((void**)&p_h2, g_h2);
    cudaGetSymbolAddress((void**)&p_wt, g_wt);

    const int smemN128 = 1024 + 65536 + 4 * 128 * 256;   // 193 KB
    const int smemN64  = 1024 + 65536 + 4 * 64 * 256;    // 129 KB
    cudaFuncSetAttribute(layer_kernel<128, 2, false, true, false, false>,
                         cudaFuncAttributeMaxDynamicSharedMemorySize, smemN128);
    cudaFuncSetAttribute(layer_kernel<128, 3, true, false, true, false>,
                         cudaFuncAttributeMaxDynamicSharedMemorySize, smemN128);
    cudaFuncSetAttribute(layer_kernel<64, 3, false, false, true, true>,
                         cudaFuncAttributeMaxDynamicSharedMemorySize, smemN64);

    int nb = (n + 1023) / 1024;
    int gblocks = (n * 32 + 255) / 256;   // gather: 1 warp/node
    int mblocks = (n + 127) / 128;        // layer kernels: 128 rows/CTA
    #define WT(i) (p_wt + (size_t)(i) * 4096)

    // weight prep + CSR build (rank-based fill, no cursor atomics)
    prep_w_kernel<<<8, 256>>>(w1n, w1r, w2n, w2r, wr1, wfn, wfr, wr2);
    init_kernel<<<(n + 255) / 256, 256>>>((const unsigned long long*)ei, n);
    hist_kernel<<<(E + 255) / 256, 256>>>(ei, E);
    bsum_kernel<<<nb, 256>>>(n);
    scan2_kernel<<<nb, 1024>>>(n);
    fill_kernel<<<(E + 255) / 256, 256>>>(ei, E);

    // layer 1: h1 = relu(mean(z) @ w1n + z @ w1r + b1)
    gather_mean_kernel<<<gblocks, 256>>>(z, p_mean, n);
    layer_kernel<128, 2, false, true, false, false><<<mblocks, 256, smemN128>>>(
        p_mean, z, nullptr, WT(0), WT(1), nullptr, b1, nullptr, p_h1, n);

    // layer 2: h2 = relu(mean(h1) @ w2n + h1 @ w2r + b2) + z @ wr1 + br1
    gather_mean_kernel<<<gblocks, 256>>>(p_h1, p_mean, n);
    layer_kernel<128, 3, true, false, true, false><<<mblocks, 256, smemN128>>>(
        p_mean, p_h1, z, WT(2), WT(3), WT(4), b2, br1, p_h2, n);

    // layer 3: out = mean(h2) @ wfn + h2 @ wfr + z @ wr2 + bf + br2; sigmoid[:8]
    gather_mean_kernel<<<gblocks, 256>>>(p_h2, p_mean, n);
    layer_kernel<64, 3, false, false, true, true><<<mblocks, 256, smemN64>>>(
        p_mean, p_h2, z, WT(5), WT(6), WT(7), bf, br2, out, n);
}